// round 16
// baseline (speedup 1.0000x reference)
#include <cuda_runtime.h>
#include <cuda_fp16.h>

#define BATCH 8
#define HH 512
#define WW 512
#define W2 (WW / 2)
#define PLANE (HH * WW)
#define NP (BATCH * PLANE)
#define RAD 15
#define INV_K2 (1.0f / 961.0f)
#define EPSV 1e-6f
#define SEG 16        // rows per vertical segment (k_v2)
#define SEGV 16       // rows per vertical segment (k_vh)
#define SPAD 544
#define PADI(i) ((i) + ((i) >> 4))

// -------- scratch (device globals) --------
// 0=I, 1=I*I, 2..4=p_c, 5..7=I*p_c   (fp16 planes, fp32 accumulation downstream)
__device__ __half g_hsum[8][NP];   // 32 MB
__device__ __half g_gray[NP];      // 4 MB
__device__ __half g_hsum2[6][NP];  // 24 MB

__device__ __forceinline__ float iscan(float v, int lane) {
#pragma unroll
    for (int o = 1; o < 32; o <<= 1) {
        float n = __shfl_up_sync(0xffffffffu, v, o);
        if (lane >= o) v += n;
    }
    return v;
}

// ============================================================================
// K1: horizontal pass (frozen R12 config). Chunk-local scan, register-direct
// loads, coalesced fp16 stores. 1 warp/row, 4 rows/block.
// ============================================================================
__global__ __launch_bounds__(128) void k_h1(const float* __restrict__ guide,
                                            const float* __restrict__ input) {
    const int warp = threadIdx.x >> 5;
    const int lane = threadIdx.x & 31;
    const int grow = blockIdx.x * 4 + warp;
    const int b = grow >> 9;
    const int r = grow & 511;

    const float* gR = guide + ((size_t)(b * 3 + 0) * HH + r) * WW;
    const float* gG = guide + ((size_t)(b * 3 + 1) * HH + r) * WW;
    const float* gB = guide + ((size_t)(b * 3 + 2) * HH + r) * WW;
    const float* p0 = input + ((size_t)(b * 3 + 0) * HH + r) * WW;
    const float* p1 = input + ((size_t)(b * 3 + 1) * HH + r) * WW;
    const float* p2 = input + ((size_t)(b * 3 + 2) * HH + r) * WW;

    __shared__ float sp[4][SPAD];
    float* pref = sp[warp];

    const size_t rowOff = (size_t)grow * WW;
    const int cb = lane * 16;

    float gv[16], pv[16], lp[16];

#pragma unroll
    for (int j = 0; j < 4; j++) {
        float4 rv = ((const float4*)(gR + cb))[j];
        float4 gg = ((const float4*)(gG + cb))[j];
        float4 bv = ((const float4*)(gB + cb))[j];
        gv[4*j+0] = 0.299f * rv.x + 0.587f * gg.x + 0.114f * bv.x;
        gv[4*j+1] = 0.299f * rv.y + 0.587f * gg.y + 0.114f * bv.y;
        gv[4*j+2] = 0.299f * rv.z + 0.587f * gg.z + 0.114f * bv.z;
        gv[4*j+3] = 0.299f * rv.w + 0.587f * gg.w + 0.114f * bv.w;
    }
    {
        __half2 h[8];
#pragma unroll
        for (int j = 0; j < 8; j++) h[j] = __floats2half2_rn(gv[2*j], gv[2*j+1]);
        uint4* dst = reinterpret_cast<uint4*>(g_gray + rowOff + cb);
        dst[0] = *reinterpret_cast<uint4*>(&h[0]);
        dst[1] = *reinterpret_cast<uint4*>(&h[4]);
    }

    auto scan_store = [&](__half* __restrict__ outp) {
        float tot = lp[15];
        float ex = iscan(tot, lane) - tot;
#pragma unroll
        for (int k = 0; k < 16; k++) pref[PADI(cb + k)] = ex + lp[k];
        __syncwarp();
#pragma unroll
        for (int i = 0; i < 16; i++) {
            int x = i * 32 + lane;
            int hx = (x + RAD > WW - 1) ? (WW - 1) : (x + RAD);
            float hi = pref[PADI(hx)];
            float lo = (x >= RAD + 1) ? pref[PADI(x - RAD - 1)] : 0.f;
            outp[x] = __float2half_rn(hi - lo);
        }
        __syncwarp();
    };

    { float a = 0.f;
#pragma unroll
      for (int k = 0; k < 16; k++) { a += gv[k]; lp[k] = a; } }
    scan_store(g_hsum[0] + rowOff);
    { float a = 0.f;
#pragma unroll
      for (int k = 0; k < 16; k++) { a += gv[k] * gv[k]; lp[k] = a; } }
    scan_store(g_hsum[1] + rowOff);

    const float* pc[3] = { p0, p1, p2 };
    const int qp[3] = { 2, 3, 4 };
    const int qip[3] = { 5, 6, 7 };
#pragma unroll
    for (int c = 0; c < 3; c++) {
#pragma unroll
        for (int j = 0; j < 4; j++) {
            float4 v = ((const float4*)(pc[c] + cb))[j];
            pv[4*j+0] = v.x; pv[4*j+1] = v.y; pv[4*j+2] = v.z; pv[4*j+3] = v.w;
        }
        { float a = 0.f;
#pragma unroll
          for (int k = 0; k < 16; k++) { a += pv[k]; lp[k] = a; } }
        scan_store(g_hsum[qp[c]] + rowOff);
        { float a = 0.f;
#pragma unroll
          for (int k = 0; k < 16; k++) { a += gv[k] * pv[k]; lp[k] = a; } }
        scan_store(g_hsum[qip[c]] + rowOff);
    }
}

// ============================================================================
// K2 (fused vertical+horizontal on a,b) — SPLIT BY CHANNEL.
// Block handles ONE channel c: vertical sums of 4 planes (I, I^2, p_c, I*p_c),
// a_c,b_c per row, block scan of 2 quantities, write 2 hsum2 planes.
// 256 thr, 2 cols/thread, SEGV=16, 2 barriers/row, slide prefetch.
// grid (HH/SEGV, BATCH*3) = (32, 24) = 768 blocks (3x warps vs R12).
// ============================================================================
__global__ __launch_bounds__(256) void k_vh() {
    const int tid  = threadIdx.x;
    const int warp = tid >> 5;
    const int lane = tid & 31;
    const int r0 = blockIdx.x * SEGV;
    const int zc = blockIdx.y;
    const int b  = zc / 3;
    const int c  = zc - b * 3;
    const int base = b * (PLANE / 2) + tid;   // half2 index

    const __half2* __restrict__ pI  = (const __half2*)g_hsum[0];
    const __half2* __restrict__ pII = (const __half2*)g_hsum[1];
    const __half2* __restrict__ pP  = (const __half2*)g_hsum[2 + c];
    const __half2* __restrict__ pIP = (const __half2*)g_hsum[5 + c];

    __shared__ float s_pref[2][2][WW];   // 8 KB
    __shared__ float s_wtot[2][2][8];

    float2 s[4];
#pragma unroll
    for (int q = 0; q < 4; q++) { s[q].x = 0.f; s[q].y = 0.f; }

    const int jstart = (r0 - RAD < 0) ? 0 : (r0 - RAD);
#pragma unroll 4
    for (int j = jstart; j <= r0 + RAD; j++) {
        const int off = base + j * W2;
        float2 v0 = __half22float2(pI[off]);
        float2 v1 = __half22float2(pII[off]);
        float2 v2 = __half22float2(pP[off]);
        float2 v3 = __half22float2(pIP[off]);
        s[0].x += v0.x; s[0].y += v0.y;
        s[1].x += v1.x; s[1].y += v1.y;
        s[2].x += v2.x; s[2].y += v2.y;
        s[3].x += v3.x; s[3].y += v3.y;
    }

    for (int i = 0; i < SEGV; i++) {
        const int row = r0 + i;
        const int off = base + row * W2;
        const int bu = i & 1;

        // ---- prefetch slide loads ----
        const int lead  = row + RAD + 1;
        const int trail = row - RAD;
        const bool hl = lead < HH;
        const bool ht = trail >= 0;
        float2 ldv[4], trv[4];
        if (hl) {
            const int lo = base + lead * W2;
            ldv[0] = __half22float2(pI[lo]);
            ldv[1] = __half22float2(pII[lo]);
            ldv[2] = __half22float2(pP[lo]);
            ldv[3] = __half22float2(pIP[lo]);
        }
        if (ht) {
            const int to = base + trail * W2;
            trv[0] = __half22float2(pI[to]);
            trv[1] = __half22float2(pII[to]);
            trv[2] = __half22float2(pP[to]);
            trv[3] = __half22float2(pIP[to]);
        }

        // ---- a,b for this channel ----
        float2 ab[2];
        {
            float mIx = s[0].x * INV_K2, mIy = s[0].y * INV_K2;
            float cIx = s[1].x * INV_K2, cIy = s[1].y * INV_K2;
            float ivx = 1.f / (cIx - mIx * mIx + EPSV);
            float ivy = 1.f / (cIy - mIy * mIy + EPSV);
            float mpx  = s[2].x * INV_K2, mpy  = s[2].y * INV_K2;
            float cIpx = s[3].x * INV_K2, cIpy = s[3].y * INV_K2;
            float ax = (cIpx - mIx * mpx) * ivx;
            float ay = (cIpy - mIy * mpy) * ivy;
            ab[0].x = ax;             ab[0].y = ay;
            ab[1].x = mpx - ax * mIx; ab[1].y = mpy - ay * mIy;
        }

        // ---- block prefix scan of 2 quantities (2 barriers) ----
        float tq[2], wv[2];
#pragma unroll
        for (int q = 0; q < 2; q++) {
            tq[q] = ab[q].x + ab[q].y;
            wv[q] = iscan(tq[q], lane);
            if (lane == 31) s_wtot[bu][q][warp] = wv[q];
        }
        __syncthreads();
#pragma unroll
        for (int q = 0; q < 2; q++) {
            float carry = 0.f;
#pragma unroll
            for (int w = 0; w < 7; w++) if (w < warp) carry += s_wtot[bu][q][w];
            float ex = wv[q] - tq[q] + carry;
            float2 pr;
            pr.x = ex + ab[q].x;
            pr.y = pr.x + ab[q].y;
            ((float2*)s_pref[bu][q])[tid] = pr;
        }
        __syncthreads();

        // ---- horizontal box sums -> hsum2[c], hsum2[3+c] ----
        const int x0 = 2 * tid, x1 = x0 + 1;
        const int h0 = (x0 + RAD > WW - 1) ? (WW - 1) : (x0 + RAD);
        const int h1 = (x1 + RAD > WW - 1) ? (WW - 1) : (x1 + RAD);
        {
            float lo0 = (x0 >= RAD + 1) ? s_pref[bu][0][x0 - RAD - 1] : 0.f;
            float lo1 = (x1 >= RAD + 1) ? s_pref[bu][0][x1 - RAD - 1] : 0.f;
            ((__half2*)g_hsum2[c])[off] =
                __floats2half2_rn(s_pref[bu][0][h0] - lo0, s_pref[bu][0][h1] - lo1);
            float mo0 = (x0 >= RAD + 1) ? s_pref[bu][1][x0 - RAD - 1] : 0.f;
            float mo1 = (x1 >= RAD + 1) ? s_pref[bu][1][x1 - RAD - 1] : 0.f;
            ((__half2*)g_hsum2[3 + c])[off] =
                __floats2half2_rn(s_pref[bu][1][h0] - mo0, s_pref[bu][1][h1] - mo1);
        }

        // ---- apply slide ----
        if (hl) {
#pragma unroll
            for (int q = 0; q < 4; q++) { s[q].x += ldv[q].x; s[q].y += ldv[q].y; }
        }
        if (ht) {
#pragma unroll
            for (int q = 0; q < 4; q++) { s[q].x -= trv[q].x; s[q].y -= trv[q].y; }
        }
    }
}

// ============================================================================
// K3: vertical running sums on fp16 hsum2 — column-split (R15 config, frozen).
// 128 thr x 2 cols, grid (2, HH/SEG, BATCH*3) = 1536 blocks.
// ============================================================================
__global__ __launch_bounds__(128) void k_v2(float* __restrict__ out) {
    const int t  = blockIdx.x * 128 + threadIdx.x;   // half2 col index 0..255
    const int zc = blockIdx.z;
    const int b  = zc / 3;
    const int c  = zc - b * 3;
    const int r0 = blockIdx.y * SEG;
    const int base = b * (PLANE / 2) + t;

    const __half2* __restrict__ pa = (const __half2*)g_hsum2[c];
    const __half2* __restrict__ pb = (const __half2*)g_hsum2[3 + c];
    const __half2* __restrict__ pg = (const __half2*)g_gray;
    float2* __restrict__ po = (float2*)(out + (size_t)zc * PLANE);

    float2 sa = make_float2(0.f, 0.f);
    float2 sb = make_float2(0.f, 0.f);

    const int jstart = (r0 - RAD < 0) ? 0 : (r0 - RAD);
#pragma unroll 4
    for (int j = jstart; j <= r0 + RAD; j++) {
        const int off = base + j * W2;
        float2 va = __half22float2(pa[off]);
        float2 vb = __half22float2(pb[off]);
        sa.x += va.x; sa.y += va.y;
        sb.x += vb.x; sb.y += vb.y;
    }

#pragma unroll 4
    for (int i = 0; i < SEG; i++) {
        const int row = r0 + i;
        const int off = base + row * W2;

        const int lead  = row + RAD + 1;
        const int trail = row - RAD;
        const bool hl = lead < HH;
        const bool ht = trail >= 0;
        float2 la, lb, ta, tb;
        if (hl) {
            const int lo = base + lead * W2;
            la = __half22float2(pa[lo]); lb = __half22float2(pb[lo]);
        }
        if (ht) {
            const int to = base + trail * W2;
            ta = __half22float2(pa[to]); tb = __half22float2(pb[to]);
        }

        const float2 gr = __half22float2(pg[off]);
        float2 o;
        o.x = (sa.x * INV_K2) * gr.x + sb.x * INV_K2;
        o.y = (sa.y * INV_K2) * gr.y + sb.y * INV_K2;
        po[row * W2 + t] = o;

        if (hl) {
            sa.x += la.x; sa.y += la.y;
            sb.x += lb.x; sb.y += lb.y;
        }
        if (ht) {
            sa.x -= ta.x; sa.y -= ta.y;
            sb.x -= tb.x; sb.y -= tb.y;
        }
    }
}

// ============================================================================
extern "C" void kernel_launch(void* const* d_in, const int* in_sizes, int n_in,
                              void* d_out, int out_size) {
    const float* guide = (const float*)d_in[0];
    const float* input = (const float*)d_in[1];
    float* out = (float*)d_out;

    k_h1<<<BATCH * HH / 4, 128>>>(guide, input);
    k_vh<<<dim3(HH / SEGV, BATCH * 3), 256>>>();
    k_v2<<<dim3(2, HH / SEG, BATCH * 3), 128>>>(out);
}

// round 17
// speedup vs baseline: 1.0713x; 1.0713x over previous
#include <cuda_runtime.h>
#include <cuda_fp16.h>

#define BATCH 8
#define HH 512
#define WW 512
#define W2 (WW / 2)
#define PLANE (HH * WW)
#define NP (BATCH * PLANE)
#define RAD 15
#define INV_K2 (1.0f / 961.0f)
#define EPSV 1e-6f
#define SEG 16        // rows per vertical segment (k_v2)
#define SEGV 16       // rows per vertical segment (k_vh)
#define SPAD 544
#define PADI(i) ((i) + ((i) >> 4))

// -------- scratch (device globals) --------
// 0=I, 1=I*I, 2..4=p_c, 5..7=I*p_c   (fp16 planes, fp32 accumulation downstream)
__device__ __half g_hsum[8][NP];   // 32 MB
__device__ __half g_gray[NP];      // 4 MB
__device__ __half g_hsum2[6][NP];  // 24 MB

__device__ __forceinline__ float iscan(float v, int lane) {
#pragma unroll
    for (int o = 1; o < 32; o <<= 1) {
        float n = __shfl_up_sync(0xffffffffu, v, o);
        if (lane >= o) v += n;
    }
    return v;
}

// ============================================================================
// K1: horizontal pass (frozen R12 config — best of 6 measured variants).
// Chunk-local scan, register-direct loads, coalesced fp16 stores.
// 1 warp/row, 4 rows/block. grid 1024 x 128.
// ============================================================================
__global__ __launch_bounds__(128) void k_h1(const float* __restrict__ guide,
                                            const float* __restrict__ input) {
    const int warp = threadIdx.x >> 5;
    const int lane = threadIdx.x & 31;
    const int grow = blockIdx.x * 4 + warp;
    const int b = grow >> 9;
    const int r = grow & 511;

    const float* gR = guide + ((size_t)(b * 3 + 0) * HH + r) * WW;
    const float* gG = guide + ((size_t)(b * 3 + 1) * HH + r) * WW;
    const float* gB = guide + ((size_t)(b * 3 + 2) * HH + r) * WW;
    const float* p0 = input + ((size_t)(b * 3 + 0) * HH + r) * WW;
    const float* p1 = input + ((size_t)(b * 3 + 1) * HH + r) * WW;
    const float* p2 = input + ((size_t)(b * 3 + 2) * HH + r) * WW;

    __shared__ float sp[4][SPAD];
    float* pref = sp[warp];

    const size_t rowOff = (size_t)grow * WW;
    const int cb = lane * 16;

    float gv[16], pv[16], lp[16];

#pragma unroll
    for (int j = 0; j < 4; j++) {
        float4 rv = ((const float4*)(gR + cb))[j];
        float4 gg = ((const float4*)(gG + cb))[j];
        float4 bv = ((const float4*)(gB + cb))[j];
        gv[4*j+0] = 0.299f * rv.x + 0.587f * gg.x + 0.114f * bv.x;
        gv[4*j+1] = 0.299f * rv.y + 0.587f * gg.y + 0.114f * bv.y;
        gv[4*j+2] = 0.299f * rv.z + 0.587f * gg.z + 0.114f * bv.z;
        gv[4*j+3] = 0.299f * rv.w + 0.587f * gg.w + 0.114f * bv.w;
    }
    {
        __half2 h[8];
#pragma unroll
        for (int j = 0; j < 8; j++) h[j] = __floats2half2_rn(gv[2*j], gv[2*j+1]);
        uint4* dst = reinterpret_cast<uint4*>(g_gray + rowOff + cb);
        dst[0] = *reinterpret_cast<uint4*>(&h[0]);
        dst[1] = *reinterpret_cast<uint4*>(&h[4]);
    }

    auto scan_store = [&](__half* __restrict__ outp) {
        float tot = lp[15];
        float ex = iscan(tot, lane) - tot;
#pragma unroll
        for (int k = 0; k < 16; k++) pref[PADI(cb + k)] = ex + lp[k];
        __syncwarp();
#pragma unroll
        for (int i = 0; i < 16; i++) {
            int x = i * 32 + lane;
            int hx = (x + RAD > WW - 1) ? (WW - 1) : (x + RAD);
            float hi = pref[PADI(hx)];
            float lo = (x >= RAD + 1) ? pref[PADI(x - RAD - 1)] : 0.f;
            outp[x] = __float2half_rn(hi - lo);
        }
        __syncwarp();
    };

    { float a = 0.f;
#pragma unroll
      for (int k = 0; k < 16; k++) { a += gv[k]; lp[k] = a; } }
    scan_store(g_hsum[0] + rowOff);
    { float a = 0.f;
#pragma unroll
      for (int k = 0; k < 16; k++) { a += gv[k] * gv[k]; lp[k] = a; } }
    scan_store(g_hsum[1] + rowOff);

    const float* pc[3] = { p0, p1, p2 };
    const int qp[3] = { 2, 3, 4 };
    const int qip[3] = { 5, 6, 7 };
#pragma unroll
    for (int c = 0; c < 3; c++) {
#pragma unroll
        for (int j = 0; j < 4; j++) {
            float4 v = ((const float4*)(pc[c] + cb))[j];
            pv[4*j+0] = v.x; pv[4*j+1] = v.y; pv[4*j+2] = v.z; pv[4*j+3] = v.w;
        }
        { float a = 0.f;
#pragma unroll
          for (int k = 0; k < 16; k++) { a += pv[k]; lp[k] = a; } }
        scan_store(g_hsum[qp[c]] + rowOff);
        { float a = 0.f;
#pragma unroll
          for (int k = 0; k < 16; k++) { a += gv[k] * pv[k]; lp[k] = a; } }
        scan_store(g_hsum[qip[c]] + rowOff);
    }
}

// ============================================================================
// K2 (fused vertical+horizontal on a,b): FROZEN R12 form — best of 7 measured
// variants. 256 thr, 2 cols/thread (half2 loads, fp32 accum), SEGV=16,
// 2 barriers/row, double-buffered smem, slide prefetch. grid (32, 8).
// ============================================================================
__global__ __launch_bounds__(256) void k_vh() {
    const int tid  = threadIdx.x;
    const int warp = tid >> 5;
    const int lane = tid & 31;
    const int r0 = blockIdx.x * SEGV;
    const int b  = blockIdx.y;
    const int base = b * (PLANE / 2) + tid;   // half2 index

    __shared__ float s_pref[2][6][WW];   // 24 KB
    __shared__ float s_wtot[2][6][8];

    float2 s[8];
#pragma unroll
    for (int q = 0; q < 8; q++) { s[q].x = 0.f; s[q].y = 0.f; }

    const int jstart = (r0 - RAD < 0) ? 0 : (r0 - RAD);
#pragma unroll 4
    for (int j = jstart; j <= r0 + RAD; j++) {
        const int off = base + j * W2;
#pragma unroll
        for (int q = 0; q < 8; q++) {
            float2 v = __half22float2(((const __half2*)g_hsum[q])[off]);
            s[q].x += v.x; s[q].y += v.y;
        }
    }

    for (int i = 0; i < SEGV; i++) {
        const int row = r0 + i;
        const int off = base + row * W2;
        const int bu = i & 1;

        const int lead  = row + RAD + 1;
        const int trail = row - RAD;
        const bool hl = lead < HH;
        const bool ht = trail >= 0;
        float2 ldv[8], trv[8];
        if (hl) {
            const int lo = base + lead * W2;
#pragma unroll
            for (int q = 0; q < 8; q++)
                ldv[q] = __half22float2(((const __half2*)g_hsum[q])[lo]);
        }
        if (ht) {
            const int to = base + trail * W2;
#pragma unroll
            for (int q = 0; q < 8; q++)
                trv[q] = __half22float2(((const __half2*)g_hsum[q])[to]);
        }

        float2 ab[6];
        {
            float mIx = s[0].x * INV_K2, mIy = s[0].y * INV_K2;
            float cIx = s[1].x * INV_K2, cIy = s[1].y * INV_K2;
            float ivx = 1.f / (cIx - mIx * mIx + EPSV);
            float ivy = 1.f / (cIy - mIy * mIy + EPSV);
#pragma unroll
            for (int c = 0; c < 3; c++) {
                float mpx  = s[2 + c].x * INV_K2, mpy  = s[2 + c].y * INV_K2;
                float cIpx = s[5 + c].x * INV_K2, cIpy = s[5 + c].y * INV_K2;
                float ax = (cIpx - mIx * mpx) * ivx;
                float ay = (cIpy - mIy * mpy) * ivy;
                ab[c].x = ax;                 ab[c].y = ay;
                ab[3 + c].x = mpx - ax * mIx; ab[3 + c].y = mpy - ay * mIy;
            }
        }

        float tq[6], wv[6];
#pragma unroll
        for (int q = 0; q < 6; q++) {
            tq[q] = ab[q].x + ab[q].y;
            wv[q] = iscan(tq[q], lane);
            if (lane == 31) s_wtot[bu][q][warp] = wv[q];
        }
        __syncthreads();
#pragma unroll
        for (int q = 0; q < 6; q++) {
            float carry = 0.f;
#pragma unroll
            for (int w = 0; w < 7; w++) if (w < warp) carry += s_wtot[bu][q][w];
            float ex = wv[q] - tq[q] + carry;
            float2 pr;
            pr.x = ex + ab[q].x;
            pr.y = pr.x + ab[q].y;
            ((float2*)s_pref[bu][q])[tid] = pr;
        }
        __syncthreads();

        const int x0 = 2 * tid, x1 = x0 + 1;
        const int h0 = (x0 + RAD > WW - 1) ? (WW - 1) : (x0 + RAD);
        const int h1 = (x1 + RAD > WW - 1) ? (WW - 1) : (x1 + RAD);
#pragma unroll
        for (int q = 0; q < 6; q++) {
            float lo0 = (x0 >= RAD + 1) ? s_pref[bu][q][x0 - RAD - 1] : 0.f;
            float lo1 = (x1 >= RAD + 1) ? s_pref[bu][q][x1 - RAD - 1] : 0.f;
            __half2 hv = __floats2half2_rn(s_pref[bu][q][h0] - lo0,
                                           s_pref[bu][q][h1] - lo1);
            ((__half2*)g_hsum2[q])[off] = hv;
        }

        if (hl) {
#pragma unroll
            for (int q = 0; q < 8; q++) { s[q].x += ldv[q].x; s[q].y += ldv[q].y; }
        }
        if (ht) {
#pragma unroll
            for (int q = 0; q < 8; q++) { s[q].x -= trv[q].x; s[q].y -= trv[q].y; }
        }
    }
}

// ============================================================================
// K3: vertical running sums on fp16 hsum2 — column-split (R15 config).
// 128 thr x 2 cols (half2 loads, fp32 accum), 256-col half per block.
// grid (2, HH/SEG, BATCH*3) = 1536 blocks.
// ============================================================================
__global__ __launch_bounds__(128) void k_v2(float* __restrict__ out) {
    const int t  = blockIdx.x * 128 + threadIdx.x;   // half2 col index 0..255
    const int zc = blockIdx.z;
    const int b  = zc / 3;
    const int c  = zc - b * 3;
    const int r0 = blockIdx.y * SEG;
    const int base = b * (PLANE / 2) + t;

    const __half2* __restrict__ pa = (const __half2*)g_hsum2[c];
    const __half2* __restrict__ pb = (const __half2*)g_hsum2[3 + c];
    const __half2* __restrict__ pg = (const __half2*)g_gray;
    float2* __restrict__ po = (float2*)(out + (size_t)zc * PLANE);

    float2 sa = make_float2(0.f, 0.f);
    float2 sb = make_float2(0.f, 0.f);

    const int jstart = (r0 - RAD < 0) ? 0 : (r0 - RAD);
#pragma unroll 4
    for (int j = jstart; j <= r0 + RAD; j++) {
        const int off = base + j * W2;
        float2 va = __half22float2(pa[off]);
        float2 vb = __half22float2(pb[off]);
        sa.x += va.x; sa.y += va.y;
        sb.x += vb.x; sb.y += vb.y;
    }

#pragma unroll 4
    for (int i = 0; i < SEG; i++) {
        const int row = r0 + i;
        const int off = base + row * W2;

        const int lead  = row + RAD + 1;
        const int trail = row - RAD;
        const bool hl = lead < HH;
        const bool ht = trail >= 0;
        float2 la, lb, ta, tb;
        if (hl) {
            const int lo = base + lead * W2;
            la = __half22float2(pa[lo]); lb = __half22float2(pb[lo]);
        }
        if (ht) {
            const int to = base + trail * W2;
            ta = __half22float2(pa[to]); tb = __half22float2(pb[to]);
        }

        const float2 gr = __half22float2(pg[off]);
        float2 o;
        o.x = (sa.x * INV_K2) * gr.x + sb.x * INV_K2;
        o.y = (sa.y * INV_K2) * gr.y + sb.y * INV_K2;
        po[row * W2 + t] = o;

        if (hl) {
            sa.x += la.x; sa.y += la.y;
            sb.x += lb.x; sb.y += lb.y;
        }
        if (ht) {
            sa.x -= ta.x; sa.y -= ta.y;
            sb.x -= tb.x; sb.y -= tb.y;
        }
    }
}

// ============================================================================
extern "C" void kernel_launch(void* const* d_in, const int* in_sizes, int n_in,
                              void* d_out, int out_size) {
    const float* guide = (const float*)d_in[0];
    const float* input = (const float*)d_in[1];
    float* out = (float*)d_out;

    k_h1<<<BATCH * HH / 4, 128>>>(guide, input);
    k_vh<<<dim3(HH / SEGV, BATCH), 256>>>();
    k_v2<<<dim3(2, HH / SEG, BATCH * 3), 128>>>(out);
}